// round 12
// baseline (speedup 1.0000x reference)
#include <cuda_runtime.h>

#define FULLMASK 0xFFFFFFFFu

// Fixed problem shape
#define BB 16
#define CC 67
#define HH 128
#define WW 128
#define PM 72
#define PR 9
#define NPLANE (HH * WW)            // 16384
#define NPIX ((size_t)BB * CC * NPLANE)

#define GRID 592                    // 4 blocks/SM x 148 SMs -- all co-resident
#define NPLANES (BB * CC)           // 1072
#define STRIP 32                    // rows per warp strip
#define HALFPLANES 536              // planes per chunk (8 batches)
#define HALFSTRIPS 2144             // strips per chunk
#define POOLB2 292                  // blocks pooling chunk1 during S2

// Scratch (no cudaMalloc allowed)
__device__ float g_pooled[BB * CC];
__device__ float g_kern[BB * 81];
__device__ unsigned int g_q[2];     // conv strip queues (reset each launch)
__device__ unsigned long long g_bar = 0ULL;   // monotonic -> replay-safe

// ---------------------------------------------------------------------------
__device__ __forceinline__ void grid_barrier() {
    __syncthreads();
    if (threadIdx.x == 0) {
        __threadfence();                                      // release
        unsigned long long old = atomicAdd(&g_bar, 1ULL);
        unsigned long long target = (old / GRID + 1ULL) * GRID;
        for (;;) {
            unsigned long long v;
            asm volatile("ld.acquire.gpu.u64 %0, [%1];" : "=l"(v) : "l"(&g_bar));
            if (v >= target) break;
            __nanosleep(32);
        }
    }
    __syncthreads();
}

__device__ __forceinline__ int refl(int h) {
    return h < 0 ? -h : (h > HH - 1 ? 2 * (HH - 1) - h : h);
}

// ---------------------------------------------------------------------------
__device__ __forceinline__ void pool_plane(const float* __restrict__ x, int bc,
                                           float* red) {
    int tid = threadIdx.x;
    const float4* xp = (const float4*)(x + (size_t)bc * NPLANE);
    float s = 0.f;
#pragma unroll
    for (int it = 0; it < 16; it++) {
        float4 v = xp[it * 256 + tid];
        s += (v.x + v.y) + (v.z + v.w);
    }
#pragma unroll
    for (int o = 16; o; o >>= 1) s += __shfl_xor_sync(FULLMASK, s, o);
    if ((tid & 31) == 0) red[tid >> 5] = s;
    __syncthreads();
    if (tid == 0) {
        float t = 0.f;
#pragma unroll
        for (int i = 0; i < 8; i++) t += red[i];
        g_pooled[bc] = t * (1.0f / (float)NPLANE);
    }
    __syncthreads();
}

__device__ __forceinline__ void kgen_batch(
    int b,
    const float* __restrict__ w_main, const float* __restrict__ w_gate_main,
    const float* __restrict__ w_rem, const float* __restrict__ w_gate_rem,
    const float* __restrict__ bmg, const float* __restrict__ bmb,
    const float* __restrict__ bmm, const float* __restrict__ bmv,
    const float* __restrict__ brg, const float* __restrict__ brb,
    const float* __restrict__ brm, const float* __restrict__ brv,
    float* sp, float* raw, float* bnv) {
    int tid = threadIdx.x;
    if (tid < CC) sp[tid] = __ldcg(&g_pooled[b * CC + tid]);
    __syncthreads();

    if (tid < PM + PR) {
        const float* wr = (tid < PM) ? (w_main + tid * CC)
                                     : (w_rem + (tid - PM) * CC);
        float s = 0.f;
#pragma unroll
        for (int c = 0; c < CC; c++) s += sp[c] * __ldg(&wr[c]);
        raw[tid] = s;
    }
    __syncthreads();

    if (tid < PM) {
        const float* wr = w_gate_main + tid * PM;
        float g = 0.f;
#pragma unroll
        for (int q = 0; q < PM; q++) g += raw[q] * __ldg(&wr[q]);
        float v = raw[tid] / (1.f + expf(-g));
        v = bmg[tid] * (v - bmm[tid]) * rsqrtf(bmv[tid] + 1e-5f) + bmb[tid];
        bnv[tid] = v;
    } else if (tid < PM + PR) {
        int p = tid - PM;
        const float* wr = w_gate_rem + p * PR;
        float g = 0.f;
#pragma unroll
        for (int q = 0; q < PR; q++) g += raw[PM + q] * __ldg(&wr[q]);
        float v = raw[PM + p] / (1.f + expf(-g));
        v = brg[p] * (v - brm[p]) * rsqrtf(brv[p] + 1e-5f) + brb[p];
        bnv[PM + p] = v;
    }
    __syncthreads();

    if (tid < PM + PR) {
        int base = (tid / 9) * 9;
        float m = -1e30f;
#pragma unroll
        for (int j = 0; j < 9; j++) m = fmaxf(m, bnv[base + j]);
        float s = 0.f;
#pragma unroll
        for (int j = 0; j < 9; j++) s += expf(bnv[base + j] - m);
        g_kern[b * 81 + tid] = expf(bnv[tid] - m) / s;
    }
    __syncthreads();
}

__device__ __forceinline__ void conv_strip(
    int strip, const float* __restrict__ x,
    float* __restrict__ out, float* __restrict__ out_high) {
    int lane = threadIdx.x & 31;
    int bc = strip >> 2;
    int r0 = (strip & 3) * STRIP;
    int b = bc / CC, c = bc % CC;

    int gidx = (c < 64) ? (c >> 3) : 8;
    const float* kp = g_kern + b * 81 + gidx * 9;
    float k0 = __ldcg(kp + 0), k1 = __ldcg(kp + 1), k2 = __ldcg(kp + 2);
    float k3 = __ldcg(kp + 3), k4 = __ldcg(kp + 4), k5 = __ldcg(kp + 5);
    float k6 = __ldcg(kp + 6), k7 = __ldcg(kp + 7), k8 = __ldcg(kp + 8);

    const float* xb = x + (size_t)bc * NPLANE;
    float* ob = out + (size_t)bc * NPLANE;
    float* hb = out_high + (size_t)bc * NPLANE;

#define HALO(v, lf, rt)                                          \
    do {                                                         \
        lf = __shfl_up_sync(FULLMASK, v.w, 1);                   \
        if (lane == 0) lf = v.y;                                 \
        rt = __shfl_down_sync(FULLMASK, v.x, 1);                 \
        if (lane == 31) rt = v.z;                                \
    } while (0)
#define LDROW(h) (((const float4*)(xb + refl(h) * WW))[lane])

    float4 vA = LDROW(r0 - 1);
    float4 vB = LDROW(r0);
    float4 vC = LDROW(r0 + 1);
    float4 p1 = LDROW(r0 + 2);
    float la, ra, lb, rb, lc2, rc2, lp1, rp1;
    HALO(vA, la, ra);
    HALO(vB, lb, rb);
    HALO(vC, lc2, rc2);
    HALO(p1, lp1, rp1);

#pragma unroll 4
    for (int i = 0; i < STRIP; i++) {
        float4 p2 = LDROW(r0 + i + 3);

        float4 acc;
        acc.x = k0 * la   + k1 * vA.x + k2 * vA.y;
        acc.y = k0 * vA.x + k1 * vA.y + k2 * vA.z;
        acc.z = k0 * vA.y + k1 * vA.z + k2 * vA.w;
        acc.w = k0 * vA.z + k1 * vA.w + k2 * ra;

        acc.x += k3 * lb   + k4 * vB.x + k5 * vB.y;
        acc.y += k3 * vB.x + k4 * vB.y + k5 * vB.z;
        acc.z += k3 * vB.y + k4 * vB.z + k5 * vB.w;
        acc.w += k3 * vB.z + k4 * vB.w + k5 * rb;

        acc.x += k6 * lc2   + k7 * vC.x + k8 * vC.y;
        acc.y += k6 * vC.x  + k7 * vC.y + k8 * vC.z;
        acc.z += k6 * vC.y  + k7 * vC.z + k8 * vC.w;
        acc.w += k6 * vC.z  + k7 * vC.w + k8 * rc2;

        float4 hi;
        hi.x = vB.x - acc.x;
        hi.y = vB.y - acc.y;
        hi.z = vB.z - acc.z;
        hi.w = vB.w - acc.w;

        int r = r0 + i;
        __stcs((float4*)(ob + r * WW) + lane, acc);
        __stcs((float4*)(hb + r * WW) + lane, hi);

        vA = vB; la = lb;  ra = rb;
        vB = vC; lb = lc2; rb = rc2;
        vC = p1; lc2 = lp1; rc2 = rp1;
        p1 = p2;
        HALO(p1, lp1, rp1);
    }
#undef LDROW
#undef HALO
}

// conv via dynamic queue: phase 0 -> strips [0,2144), phase 1 -> [2144,4288)
__device__ __forceinline__ void conv_queue(
    int phase, const float* __restrict__ x,
    float* __restrict__ out, float* __restrict__ out_high) {
    int lane = threadIdx.x & 31;
    for (;;) {
        unsigned int s = 0;
        if (lane == 0) s = atomicAdd(&g_q[phase], 1u);
        s = __shfl_sync(FULLMASK, s, 0);
        if (s >= HALFSTRIPS) break;
        conv_strip(phase * HALFSTRIPS + (int)s, x, out, out_high);
    }
}

// ---------------------------------------------------------------------------
// Persistent kernel, 5-stage 2-chunk pipeline:
//  S0: pool batches 0..7 (all blocks)
//  S1: kgen batches 0..7 (blocks 0..7)
//  S2: conv chunk0 (queue; blocks >=POOLB2 immediately)
//      || pool batches 8..15 (blocks <POOLB2, then join queue)
//  S3: kgen batches 8..15
//  S4: conv chunk1 (queue, all blocks)
// ---------------------------------------------------------------------------
__global__ void __launch_bounds__(256, 4) fused_kernel(
    const float* __restrict__ x,
    const float* __restrict__ w_main, const float* __restrict__ w_gate_main,
    const float* __restrict__ w_rem, const float* __restrict__ w_gate_rem,
    const float* __restrict__ bmg, const float* __restrict__ bmb,
    const float* __restrict__ bmm, const float* __restrict__ bmv,
    const float* __restrict__ brg, const float* __restrict__ brb,
    const float* __restrict__ brm, const float* __restrict__ brv,
    float* __restrict__ out, float* __restrict__ out_high) {
    __shared__ float red[8];
    __shared__ float sp[CC];
    __shared__ float raw[81];
    __shared__ float bnv[81];
    int bid = blockIdx.x;
    int tid = threadIdx.x;

    // ---- reset queues, then replay-safe barrier ----
    if (bid == 0 && tid < 2) g_q[tid] = 0u;
    grid_barrier();

    // ---- S0: pool chunk 0 ----
    if (bid < HALFPLANES) pool_plane(x, bid, red);
    grid_barrier();

    // ---- S1: kgen chunk 0 ----
    if (bid < 8)
        kgen_batch(bid, w_main, w_gate_main, w_rem, w_gate_rem,
                   bmg, bmb, bmm, bmv, brg, brb, brm, brv, sp, raw, bnv);
    grid_barrier();

    // ---- S2: conv chunk 0 || pool chunk 1 ----
    if (bid < POOLB2) {
        for (int p = HALFPLANES + bid; p < NPLANES; p += POOLB2)
            pool_plane(x, p, red);
    }
    conv_queue(0, x, out, out_high);
    grid_barrier();

    // ---- S3: kgen chunk 1 ----
    if (bid < 8)
        kgen_batch(8 + bid, w_main, w_gate_main, w_rem, w_gate_rem,
                   bmg, bmb, bmm, bmv, brg, brb, brm, brv, sp, raw, bnv);
    grid_barrier();

    // ---- S4: conv chunk 1 ----
    conv_queue(1, x, out, out_high);
}

// ---------------------------------------------------------------------------
extern "C" void kernel_launch(void* const* d_in, const int* in_sizes, int n_in,
                              void* d_out, int out_size) {
    const float* x            = (const float*)d_in[0];
    const float* w_main       = (const float*)d_in[1];
    const float* w_gate_main  = (const float*)d_in[2];
    const float* w_rem        = (const float*)d_in[3];
    const float* w_gate_rem   = (const float*)d_in[4];
    const float* bmg          = (const float*)d_in[5];
    const float* bmb          = (const float*)d_in[6];
    const float* bmm          = (const float*)d_in[7];
    const float* bmv          = (const float*)d_in[8];
    const float* brg          = (const float*)d_in[9];
    const float* brb          = (const float*)d_in[10];
    const float* brm          = (const float*)d_in[11];
    const float* brv          = (const float*)d_in[12];

    float* out      = (float*)d_out;
    float* out_high = out + NPIX;

    fused_kernel<<<GRID, 256>>>(x, w_main, w_gate_main, w_rem, w_gate_rem,
                                bmg, bmb, bmm, bmv, brg, brb, brm, brv,
                                out, out_high);
}

// round 13
// speedup vs baseline: 1.3870x; 1.3870x over previous
#include <cuda_runtime.h>

#define FULLMASK 0xFFFFFFFFu

// Fixed problem shape
#define BB 16
#define CC 67
#define HH 128
#define WW 128
#define PM 72
#define PR 9
#define NPLANE (HH * WW)            // 16384
#define NPIX ((size_t)BB * CC * NPLANE)

#define GRID 592                    // 4 blocks/SM x 148 SMs -- all co-resident
#define NPLANES (BB * CC)           // 1072
#define STRIP 32                    // rows per warp strip
#define NITEMS (NPLANES * 4)        // 4288 warp work items
#define NWARPS (GRID * 8)           // 4736

// Scratch (no cudaMalloc allowed)
__device__ float g_pooled[BB * CC];
__device__ float g_kern[BB * 81];
__device__ unsigned long long g_bar = 0ULL;   // monotonic -> replay-safe

// ---------------------------------------------------------------------------
__device__ __forceinline__ void grid_barrier() {
    __syncthreads();
    if (threadIdx.x == 0) {
        __threadfence();                                      // release
        unsigned long long old = atomicAdd(&g_bar, 1ULL);
        unsigned long long target = (old / GRID + 1ULL) * GRID;
        for (;;) {
            unsigned long long v;
            asm volatile("ld.acquire.gpu.u64 %0, [%1];" : "=l"(v) : "l"(&g_bar));
            if (v >= target) break;
            __nanosleep(32);
        }
    }
    __syncthreads();
}

__device__ __forceinline__ int refl(int h) {
    return h < 0 ? -h : (h > HH - 1 ? 2 * (HH - 1) - h : h);
}

// ---------------------------------------------------------------------------
// One persistent kernel: pool -> barrier -> kgen -> barrier -> conv
// Pool: each block reduces its TWO planes (bid, bid+GRID) with interleaved
// loads -> 2x MLP per thread, __ldcg to skip L1 allocation.
// ---------------------------------------------------------------------------
__global__ void __launch_bounds__(256, 4) fused_kernel(
    const float* __restrict__ x,
    const float* __restrict__ w_main, const float* __restrict__ w_gate_main,
    const float* __restrict__ w_rem, const float* __restrict__ w_gate_rem,
    const float* __restrict__ bmg, const float* __restrict__ bmb,
    const float* __restrict__ bmm, const float* __restrict__ bmv,
    const float* __restrict__ brg, const float* __restrict__ brb,
    const float* __restrict__ brm, const float* __restrict__ brv,
    float* __restrict__ out, float* __restrict__ out_high) {
    __shared__ float red0[8];
    __shared__ float red1[8];
    __shared__ float sp[CC];
    __shared__ float raw[81];
    __shared__ float bnv[81];
    int tid = threadIdx.x;

    // ================= Phase 1: dual-plane pool =====================
    {
        int bc0 = blockIdx.x;
        int bc1 = blockIdx.x + GRID;
        const float4* p0 = (const float4*)(x + (size_t)bc0 * NPLANE);
        float s0 = 0.f, s1 = 0.f;
        if (bc1 < NPLANES) {
            const float4* p1 = (const float4*)(x + (size_t)bc1 * NPLANE);
#pragma unroll
            for (int it = 0; it < 16; it++) {
                float4 a = __ldcg(&p0[it * 256 + tid]);
                float4 b = __ldcg(&p1[it * 256 + tid]);
                s0 += (a.x + a.y) + (a.z + a.w);
                s1 += (b.x + b.y) + (b.z + b.w);
            }
        } else {
#pragma unroll
            for (int it = 0; it < 16; it++) {
                float4 a = __ldcg(&p0[it * 256 + tid]);
                s0 += (a.x + a.y) + (a.z + a.w);
            }
        }
#pragma unroll
        for (int o = 16; o; o >>= 1) {
            s0 += __shfl_xor_sync(FULLMASK, s0, o);
            s1 += __shfl_xor_sync(FULLMASK, s1, o);
        }
        if ((tid & 31) == 0) { red0[tid >> 5] = s0; red1[tid >> 5] = s1; }
        __syncthreads();
        if (tid == 0) {
            float t0 = 0.f, t1 = 0.f;
#pragma unroll
            for (int i = 0; i < 8; i++) { t0 += red0[i]; t1 += red1[i]; }
            g_pooled[bc0] = t0 * (1.0f / (float)NPLANE);
            if (bc1 < NPLANES) g_pooled[bc1] = t1 * (1.0f / (float)NPLANE);
        }
        __syncthreads();
    }

    grid_barrier();

    // ================= Phase 2: kernel generation (blocks 0..15) ====
    if (blockIdx.x < BB) {
        int b = blockIdx.x;
        if (tid < CC) sp[tid] = __ldcg(&g_pooled[b * CC + tid]);
        __syncthreads();

        if (tid < PM + PR) {
            const float* wr = (tid < PM) ? (w_main + tid * CC)
                                         : (w_rem + (tid - PM) * CC);
            float s = 0.f;
#pragma unroll
            for (int c = 0; c < CC; c++) s += sp[c] * __ldg(&wr[c]);
            raw[tid] = s;
        }
        __syncthreads();

        if (tid < PM) {
            const float* wr = w_gate_main + tid * PM;
            float g = 0.f;
#pragma unroll
            for (int q = 0; q < PM; q++) g += raw[q] * __ldg(&wr[q]);
            float v = raw[tid] / (1.f + expf(-g));
            v = bmg[tid] * (v - bmm[tid]) * rsqrtf(bmv[tid] + 1e-5f) + bmb[tid];
            bnv[tid] = v;
        } else if (tid < PM + PR) {
            int p = tid - PM;
            const float* wr = w_gate_rem + p * PR;
            float g = 0.f;
#pragma unroll
            for (int q = 0; q < PR; q++) g += raw[PM + q] * __ldg(&wr[q]);
            float v = raw[PM + p] / (1.f + expf(-g));
            v = brg[p] * (v - brm[p]) * rsqrtf(brv[p] + 1e-5f) + brb[p];
            bnv[PM + p] = v;
        }
        __syncthreads();

        if (tid < PM + PR) {
            int base = (tid / 9) * 9;
            float m = -1e30f;
#pragma unroll
            for (int j = 0; j < 9; j++) m = fmaxf(m, bnv[base + j]);
            float s = 0.f;
#pragma unroll
            for (int j = 0; j < 9; j++) s += expf(bnv[base + j] - m);
            g_kern[b * 81 + tid] = expf(bnv[tid] - m) / s;
        }
        __syncthreads();
    }

    grid_barrier();

    // ================= Phase 3: warp-strip conv + residual ===========
    int lane = tid & 31;
    int gw = blockIdx.x * 8 + (tid >> 5);

#define HALO(v, lf, rt)                                          \
    do {                                                         \
        lf = __shfl_up_sync(FULLMASK, v.w, 1);                   \
        if (lane == 0) lf = v.y;                                 \
        rt = __shfl_down_sync(FULLMASK, v.x, 1);                 \
        if (lane == 31) rt = v.z;                                \
    } while (0)

    for (int it = gw; it < NITEMS; it += NWARPS) {
        int bc = it >> 2;
        int r0 = (it & 3) * STRIP;
        int b = bc / CC, c = bc % CC;

        int gidx = (c < 64) ? (c >> 3) : 8;
        const float* kp = g_kern + b * 81 + gidx * 9;
        float k0 = __ldcg(kp + 0), k1 = __ldcg(kp + 1), k2 = __ldcg(kp + 2);
        float k3 = __ldcg(kp + 3), k4 = __ldcg(kp + 4), k5 = __ldcg(kp + 5);
        float k6 = __ldcg(kp + 6), k7 = __ldcg(kp + 7), k8 = __ldcg(kp + 8);

        const float* xb = x + (size_t)bc * NPLANE;
        float* ob = out + (size_t)bc * NPLANE;
        float* hb = out_high + (size_t)bc * NPLANE;

#define LDROW(h) (((const float4*)(xb + refl(h) * WW))[lane])

        float4 vA = LDROW(r0 - 1);
        float4 vB = LDROW(r0);
        float4 vC = LDROW(r0 + 1);
        float4 p1 = LDROW(r0 + 2);
        float la, ra, lb, rb, lc2, rc2, lp1, rp1;
        HALO(vA, la, ra);
        HALO(vB, lb, rb);
        HALO(vC, lc2, rc2);
        HALO(p1, lp1, rp1);

#pragma unroll 4
        for (int i = 0; i < STRIP; i++) {
            float4 p2 = LDROW(r0 + i + 3);

            float4 acc;
            acc.x = k0 * la   + k1 * vA.x + k2 * vA.y;
            acc.y = k0 * vA.x + k1 * vA.y + k2 * vA.z;
            acc.z = k0 * vA.y + k1 * vA.z + k2 * vA.w;
            acc.w = k0 * vA.z + k1 * vA.w + k2 * ra;

            acc.x += k3 * lb   + k4 * vB.x + k5 * vB.y;
            acc.y += k3 * vB.x + k4 * vB.y + k5 * vB.z;
            acc.z += k3 * vB.y + k4 * vB.z + k5 * vB.w;
            acc.w += k3 * vB.z + k4 * vB.w + k5 * rb;

            acc.x += k6 * lc2   + k7 * vC.x + k8 * vC.y;
            acc.y += k6 * vC.x  + k7 * vC.y + k8 * vC.z;
            acc.z += k6 * vC.y  + k7 * vC.z + k8 * vC.w;
            acc.w += k6 * vC.z  + k7 * vC.w + k8 * rc2;

            float4 hi;
            hi.x = vB.x - acc.x;
            hi.y = vB.y - acc.y;
            hi.z = vB.z - acc.z;
            hi.w = vB.w - acc.w;

            int r = r0 + i;
            __stcs((float4*)(ob + r * WW) + lane, acc);
            __stcs((float4*)(hb + r * WW) + lane, hi);

            vA = vB; la = lb;  ra = rb;
            vB = vC; lb = lc2; rb = rc2;
            vC = p1; lc2 = lp1; rc2 = rp1;
            p1 = p2;
            HALO(p1, lp1, rp1);
        }
#undef LDROW
    }
#undef HALO
}

// ---------------------------------------------------------------------------
extern "C" void kernel_launch(void* const* d_in, const int* in_sizes, int n_in,
                              void* d_out, int out_size) {
    const float* x            = (const float*)d_in[0];
    const float* w_main       = (const float*)d_in[1];
    const float* w_gate_main  = (const float*)d_in[2];
    const float* w_rem        = (const float*)d_in[3];
    const float* w_gate_rem   = (const float*)d_in[4];
    const float* bmg          = (const float*)d_in[5];
    const float* bmb          = (const float*)d_in[6];
    const float* bmm          = (const float*)d_in[7];
    const float* bmv          = (const float*)d_in[8];
    const float* brg          = (const float*)d_in[9];
    const float* brb          = (const float*)d_in[10];
    const float* brm          = (const float*)d_in[11];
    const float* brv          = (const float*)d_in[12];

    float* out      = (float*)d_out;
    float* out_high = out + NPIX;

    fused_kernel<<<GRID, 256>>>(x, w_main, w_gate_main, w_rem, w_gate_rem,
                                bmg, bmb, bmm, bmv, brg, brb, brm, brv,
                                out, out_high);
}